// round 13
// baseline (speedup 1.0000x reference)
#include <cuda_runtime.h>
#include <cuda_fp16.h>
#include <cstdint>

#define B_    8
#define P_    96
#define D_    128
#define H_    256
#define NPTS  (B_*P_)          // 768
#define NPAIR (B_*P_*P_)       // 73728
#define K3    (3*H_)           // 768

// prep_all block layout: proj (heavy) first, then weight-fuse, then wi1-pack
#define NPROJ (NPTS/2)         // 384 blocks, 2 points each
#define NFUSE (K3/2)           // 384
#define NPACK (D_/2)           // 64

// ---------------- device scratch ----------------
__device__ __align__(16) uint32_t g_WcatP[(K3/2)*H_];  // fused (W2@Wf), half2 k-pair packed: [kp][n]
__device__ __align__(16) float    g_bias[H_];
__device__ __align__(16) uint32_t g_Wi1P[(D_/2)*H_];   // Wi1 product-half, half2 k-pair packed
__device__ __align__(16) float    g_As[NPTS*H_];
__device__ __align__(16) float    g_Bs[NPTS*H_];
__device__ __align__(16) float    g_At[NPTS*H_];
__device__ __align__(16) float    g_Bt[NPTS*H_];
__device__ __align__(16) float    g_Ci[NPTS*H_];
__device__ __align__(16) __half   g_Hi[(size_t)NPAIR*H_];  // relu'd interaction hidden, fp16, 37.7MB

__device__ __forceinline__ uint32_t pack_h2(float lo, float hi) {
    __half2 h = __floats2half2_rn(lo, hi);
    return *(uint32_t*)&h;
}

// ---------------- combined prep: point-proj + weights-fuse + wi1-pack -------
__global__ void __launch_bounds__(256) prep_all(
    const float* __restrict__ Ws2, const float* __restrict__ Wt2,
    const float* __restrict__ Wi2, const float* __restrict__ Wf,
    const float* __restrict__ bs2, const float* __restrict__ bt2,
    const float* __restrict__ bi2, const float* __restrict__ bff,
    const float* __restrict__ F,   const float* __restrict__ Ws1,
    const float* __restrict__ Wt1, const float* __restrict__ Wi1,
    const float* __restrict__ bs1, const float* __restrict__ bt1)
{
    int bx = blockIdx.x;
    int h  = threadIdx.x;

    if (bx < NPROJ) {
        // ---- per-point projections: 2 points per block ----
        __shared__ __align__(16) float sF[2][D_];
        int p0 = bx * 2;
        for (int t = h; t < 2*D_; t += 256) sF[t / D_][t % D_] = F[p0*D_ + t];
        __syncthreads();

        float as[2], bs[2], at[2], bt[2], ci[2];
        float b1 = bs1[h], b2 = bt1[h];
        #pragma unroll
        for (int r = 0; r < 2; r++) { as[r]=b1; bs[r]=0.f; at[r]=b2; bt[r]=0.f; ci[r]=0.f; }

        #pragma unroll 4
        for (int d = 0; d < D_; d++) {
            float wsa = Ws1[d*H_ + h];
            float wsb = Ws1[(D_ + d)*H_ + h];
            float wta = Wt1[d*H_ + h];
            float wtb = Wt1[(D_ + d)*H_ + h];
            float wib = Wi1[(D_ + d)*H_ + h];
            #pragma unroll
            for (int r = 0; r < 2; r++) {
                float f = sF[r][d];
                as[r] = fmaf(f, wsa, as[r]);
                bs[r] = fmaf(f, wsb, bs[r]);
                at[r] = fmaf(f, wta, at[r]);
                bt[r] = fmaf(f, wtb, bt[r]);
                ci[r] = fmaf(f, wib, ci[r]);
            }
        }
        #pragma unroll
        for (int r = 0; r < 2; r++) {
            int idx = (p0 + r)*H_ + h;
            g_As[idx]=as[r]; g_Bs[idx]=bs[r]; g_At[idx]=at[r]; g_Bt[idx]=bt[r]; g_Ci[idx]=ci[r];
        }
    } else if (bx < NPROJ + NFUSE) {
        // ---- fuse layer-2 with final projection, half2 k-pair pack ----
        int kp = bx - NPROJ;
        int k0 = 2*kp;
        int p  = k0 >> 8;
        int kk0 = k0 & 255, kk1 = kk0 + 1;
        const float* W2  = (p == 0) ? Ws2 : ((p == 1) ? Wt2 : Wi2);
        const float* Wfp = Wf + p * H_ * H_;
        float a0 = 0.f, a1 = 0.f;
        #pragma unroll 8
        for (int m = 0; m < H_; m++) {
            float w = Wfp[m*H_ + h];
            a0 = fmaf(W2[kk0*H_ + m], w, a0);
            a1 = fmaf(W2[kk1*H_ + m], w, a1);
        }
        g_WcatP[kp*H_ + h] = pack_h2(a0, a1);

        if (kp == 0) {
            float b = bff[h];
            for (int m = 0; m < H_; m++) {
                b = fmaf(bs2[m], Wf[m*H_ + h],          b);
                b = fmaf(bt2[m], Wf[(H_   + m)*H_ + h], b);
                b = fmaf(bi2[m], Wf[(2*H_ + m)*H_ + h], b);
            }
            g_bias[h] = b;
        }
    } else {
        // ---- pack Wi1 product-half to half2 k-pairs ----
        int kp = bx - (NPROJ + NFUSE);
        g_Wi1P[kp*H_ + h] = pack_h2(Wi1[(2*kp)*H_ + h], Wi1[(2*kp+1)*H_ + h]);
    }
}

// ---------------- kernel C: interaction hidden, fp16 mma, BK=32 -------------
// CTA = (b,i) x n-half. Hi[j,n] = relu((f_i.*f_j)@Wi1a + Ci_i + Ci_j + bi1)
// M=96, N=128, K=128 (4 iters of k32, double-buffered, 1 sync/iter).
__global__ void __launch_bounds__(384, 2) bilinear_hi(
    const float* __restrict__ F, const float* __restrict__ bi1)
{
    __shared__ __align__(16) uint32_t sP[2][16][96 + 8];    // half2, stride 104
    __shared__ __align__(16) uint32_t sW[2][16][128 + 8];   // half2, stride 136
    __shared__ float sFi[D_], sCii[128], sBi1[128];

    int bi = blockIdx.x;
    int b  = bi / P_;
    int n0 = blockIdx.y * 128;
    int tid  = threadIdx.x;
    int warp = tid >> 5, lane = tid & 31;
    int wm = warp >> 2, wn = warp & 3;      // 3 x 4
    int grp = lane >> 2, thr = lane & 3;

    for (int t = tid; t < D_; t += 384) sFi[t] = F[bi*D_ + t];
    for (int t = tid; t < 128; t += 384) {
        sCii[t] = g_Ci[bi*H_ + n0 + t];
        sBi1[t] = bi1[n0 + t];
    }
    __syncthreads();

    int j_a = tid >> 2, k_a = (tid & 3) << 3;   // j 0..95, k offset {0,8,16,24}
    const float* rowF = F + (b*P_ + j_a) * D_;

    // sW loader: 16 rows x 128 uint32 = 512 uint4; slot0 all threads, slot1 tid<128
    int w_r0 = tid >> 5,          w_c0 = (tid & 31) << 2;
    int w_r1 = (tid + 384) >> 5;  // 12..15
    bool w_act1 = tid < 128;

    float acc[2][4][4];
    #pragma unroll
    for (int mt = 0; mt < 2; mt++)
        #pragma unroll
        for (int nt = 0; nt < 4; nt++)
            #pragma unroll
            for (int c = 0; c < 4; c++) acc[mt][nt][c] = 0.f;

    // prologue prefetch (d0 = 0)
    float4 vf0 = *(const float4*)(rowF + k_a);
    float4 vf1 = *(const float4*)(rowF + k_a + 4);
    uint4  vw0 = *(const uint4*)&g_Wi1P[w_r0*H_ + n0 + w_c0];
    uint4  vw1;
    if (w_act1) vw1 = *(const uint4*)&g_Wi1P[w_r1*H_ + n0 + w_c0];

    for (int d0 = 0; d0 < D_; d0 += 32) {
        int buf = (d0 >> 5) & 1;
        int kp0 = k_a >> 1;                     // 4 k-pair rows per thread
        sP[buf][kp0+0][j_a] = pack_h2(sFi[d0+k_a+0]*vf0.x, sFi[d0+k_a+1]*vf0.y);
        sP[buf][kp0+1][j_a] = pack_h2(sFi[d0+k_a+2]*vf0.z, sFi[d0+k_a+3]*vf0.w);
        sP[buf][kp0+2][j_a] = pack_h2(sFi[d0+k_a+4]*vf1.x, sFi[d0+k_a+5]*vf1.y);
        sP[buf][kp0+3][j_a] = pack_h2(sFi[d0+k_a+6]*vf1.z, sFi[d0+k_a+7]*vf1.w);
        *(uint4*)&sW[buf][w_r0][w_c0] = vw0;
        if (w_act1) *(uint4*)&sW[buf][w_r1][w_c0] = vw1;
        __syncthreads();

        int dn = d0 + 32;
        if (dn < D_) {
            vf0 = *(const float4*)(rowF + dn + k_a);
            vf1 = *(const float4*)(rowF + dn + k_a + 4);
            vw0 = *(const uint4*)&g_Wi1P[((dn>>1) + w_r0)*H_ + n0 + w_c0];
            if (w_act1) vw1 = *(const uint4*)&g_Wi1P[((dn>>1) + w_r1)*H_ + n0 + w_c0];
        }

        #pragma unroll
        for (int s = 0; s < 2; s++) {
            int kb = s * 8;
            uint32_t af[2][4], bf[4][2];
            #pragma unroll
            for (int mt = 0; mt < 2; mt++) {
                int row = wm*32 + mt*16 + grp;
                af[mt][0] = sP[buf][kb + thr    ][row];
                af[mt][1] = sP[buf][kb + thr    ][row + 8];
                af[mt][2] = sP[buf][kb + thr + 4][row];
                af[mt][3] = sP[buf][kb + thr + 4][row + 8];
            }
            #pragma unroll
            for (int nt = 0; nt < 4; nt++) {
                int col = wn*32 + nt*8 + grp;
                bf[nt][0] = sW[buf][kb + thr    ][col];
                bf[nt][1] = sW[buf][kb + thr + 4][col];
            }
            #pragma unroll
            for (int mt = 0; mt < 2; mt++)
                #pragma unroll
                for (int nt = 0; nt < 4; nt++)
                    asm volatile(
                        "mma.sync.aligned.m16n8k16.row.col.f32.f16.f16.f32 "
                        "{%0,%1,%2,%3}, {%4,%5,%6,%7}, {%8,%9}, {%0,%1,%2,%3};"
                        : "+f"(acc[mt][nt][0]), "+f"(acc[mt][nt][1]),
                          "+f"(acc[mt][nt][2]), "+f"(acc[mt][nt][3])
                        : "r"(af[mt][0]), "r"(af[mt][1]), "r"(af[mt][2]), "r"(af[mt][3]),
                          "r"(bf[nt][0]), "r"(bf[nt][1]));
        }
    }

    // epilogue: + Ci_i + Ci_j + bi1, relu, fp16-round, store half2
    #pragma unroll
    for (int mt = 0; mt < 2; mt++) {
        #pragma unroll
        for (int half_ = 0; half_ < 2; half_++) {
            int j = wm*32 + mt*16 + grp + half_*8;
            const float* cij = g_Ci + (b*P_ + j)*H_ + n0;
            size_t obase = ((size_t)bi*P_ + j)*H_ + n0;
            #pragma unroll
            for (int nt = 0; nt < 4; nt++) {
                int col = wn*32 + nt*8 + thr*2;
                float vx = fmaxf(acc[mt][nt][half_*2+0] + sCii[col]   + cij[col]   + sBi1[col],   0.f);
                float vy = fmaxf(acc[mt][nt][half_*2+1] + sCii[col+1] + cij[col+1] + sBi1[col+1], 0.f);
                *(uint32_t*)&g_Hi[obase + col] = pack_h2(vx, vy);
            }
        }
    }
}

// ---------------- kernel D: fused GEMM, fp16 mma, BK=32 ---------------------
// CTA = (b,i) x n-half. out[j,n] = sum_k relu(H[j,k]) * Wcat[k,n] + bias, * mask.
// M=96, N=128, K=768 (24 iters of k32, double-buffered, 1 sync/iter).
#define DN 128

__global__ void __launch_bounds__(384, 2) gemm_fused(
    const float* __restrict__ dist, const float* __restrict__ mask,
    const float* __restrict__ Ws1,  float* __restrict__ out)
{
    __shared__ __align__(16) uint32_t sA[2][16][96 + 8];    // half2, stride 104
    __shared__ __align__(16) uint32_t sB[2][16][DN + 8];    // half2, stride 136
    __shared__ float sAsi[H_], sAti[H_], sW1c[H_];

    int bi = blockIdx.x;
    int b  = bi / P_;
    int n0 = blockIdx.y * DN;
    int tid  = threadIdx.x;
    int warp = tid >> 5, lane = tid & 31;
    int wm = warp >> 2, wn = warp & 3;      // 3 x 4
    int grp = lane >> 2, thr = lane & 3;

    for (int t = tid; t < H_; t += 384) {
        sAsi[t] = g_As[bi*H_ + t];
        sAti[t] = g_At[bi*H_ + t];
        sW1c[t] = Ws1[2*D_*H_ + t];        // Ws1 row 256 (distance)
    }
    __syncthreads();

    int j_a = tid >> 2, k_a = (tid & 3) << 3;   // j 0..95, k offset {0,8,16,24}
    const float*  rowBs = g_Bs + (b*P_ + j_a)*H_;
    const float*  rowBt = g_Bt + (b*P_ + j_a)*H_;
    const __half* rowHi = g_Hi + ((size_t)bi*P_ + j_a)*H_;
    float dj = dist[bi*P_ + j_a];

    int w_r0 = tid >> 5,          w_c0 = (tid & 31) << 2;
    int w_r1 = (tid + 384) >> 5;  // 12..15
    bool w_act1 = tid < 128;

    float acc[2][4][4];
    #pragma unroll
    for (int mt = 0; mt < 2; mt++)
        #pragma unroll
        for (int nt = 0; nt < 4; nt++)
            #pragma unroll
            for (int c = 0; c < 4; c++) acc[mt][nt][c] = 0.f;

    // prologue prefetch (k0 = 0). va0/va1 carry fp32 pairs for k<512; for the
    // Hi region va0 alone carries 8 halves (raw bits).
    float4 va0 = *(const float4*)(rowBs + k_a);
    float4 va1 = *(const float4*)(rowBs + k_a + 4);
    uint4  vb0 = *(const uint4*)&g_WcatP[w_r0*H_ + n0 + w_c0];
    uint4  vb1;
    if (w_act1) vb1 = *(const uint4*)&g_WcatP[w_r1*H_ + n0 + w_c0];

    for (int k0 = 0; k0 < K3; k0 += 32) {
        int buf = (k0 >> 5) & 1;
        int kp0 = k_a >> 1;
        if (k0 < 256) {
            int kk = k0 + k_a;
            sA[buf][kp0+0][j_a] = pack_h2(fmaxf(sAsi[kk+0] + va0.x + dj*sW1c[kk+0], 0.f),
                                          fmaxf(sAsi[kk+1] + va0.y + dj*sW1c[kk+1], 0.f));
            sA[buf][kp0+1][j_a] = pack_h2(fmaxf(sAsi[kk+2] + va0.z + dj*sW1c[kk+2], 0.f),
                                          fmaxf(sAsi[kk+3] + va0.w + dj*sW1c[kk+3], 0.f));
            sA[buf][kp0+2][j_a] = pack_h2(fmaxf(sAsi[kk+4] + va1.x + dj*sW1c[kk+4], 0.f),
                                          fmaxf(sAsi[kk+5] + va1.y + dj*sW1c[kk+5], 0.f));
            sA[buf][kp0+3][j_a] = pack_h2(fmaxf(sAsi[kk+6] + va1.z + dj*sW1c[kk+6], 0.f),
                                          fmaxf(sAsi[kk+7] + va1.w + dj*sW1c[kk+7], 0.f));
        } else if (k0 < 512) {
            int kk = k0 - 256 + k_a;
            sA[buf][kp0+0][j_a] = pack_h2(fmaxf(sAti[kk+0] + va0.x, 0.f),
                                          fmaxf(sAti[kk+1] + va0.y, 0.f));
            sA[buf][kp0+1][j_a] = pack_h2(fmaxf(sAti[kk+2] + va0.z, 0.f),
                                          fmaxf(sAti[kk+3] + va0.w, 0.f));
            sA[buf][kp0+2][j_a] = pack_h2(fmaxf(sAti[kk+4] + va1.x, 0.f),
                                          fmaxf(sAti[kk+5] + va1.y, 0.f));
            sA[buf][kp0+3][j_a] = pack_h2(fmaxf(sAti[kk+6] + va1.z, 0.f),
                                          fmaxf(sAti[kk+7] + va1.w, 0.f));
        } else {
            sA[buf][kp0+0][j_a] = __float_as_uint(va0.x);   // already relu'd fp16 pairs
            sA[buf][kp0+1][j_a] = __float_as_uint(va0.y);
            sA[buf][kp0+2][j_a] = __float_as_uint(va0.z);
            sA[buf][kp0+3][j_a] = __float_as_uint(va0.w);
        }
        *(uint4*)&sB[buf][w_r0][w_c0] = vb0;
        if (w_act1) *(uint4*)&sB[buf][w_r1][w_c0] = vb1;
        __syncthreads();

        int kn = k0 + 32;
        if (kn < K3) {
            if (kn < 512) {
                const float* src = (kn < 256) ? (rowBs + kn) : (rowBt + (kn - 256));
                va0 = *(const float4*)(src + k_a);
                va1 = *(const float4*)(src + k_a + 4);
            } else {
                va0 = *(const float4*)(const void*)(rowHi + (kn - 512) + k_a);
            }
            vb0 = *(const uint4*)&g_WcatP[((kn>>1) + w_r0)*H_ + n0 + w_c0];
            if (w_act1) vb1 = *(const uint4*)&g_WcatP[((kn>>1) + w_r1)*H_ + n0 + w_c0];
        }

        #pragma unroll
        for (int s = 0; s < 2; s++) {
            int kb = s * 8;
            uint32_t af[2][4], bf[4][2];
            #pragma unroll
            for (int mt = 0; mt < 2; mt++) {
                int row = wm*32 + mt*16 + grp;
                af[mt][0] = sA[buf][kb + thr    ][row];
                af[mt][1] = sA[buf][kb + thr    ][row + 8];
                af[mt][2] = sA[buf][kb + thr + 4][row];
                af[mt][3] = sA[buf][kb + thr + 4][row + 8];
            }
            #pragma unroll
            for (int nt = 0; nt < 4; nt++) {
                int col = wn*32 + nt*8 + grp;
                bf[nt][0] = sB[buf][kb + thr    ][col];
                bf[nt][1] = sB[buf][kb + thr + 4][col];
            }
            #pragma unroll
            for (int mt = 0; mt < 2; mt++)
                #pragma unroll
                for (int nt = 0; nt < 4; nt++)
                    asm volatile(
                        "mma.sync.aligned.m16n8k16.row.col.f32.f16.f16.f32 "
                        "{%0,%1,%2,%3}, {%4,%5,%6,%7}, {%8,%9}, {%0,%1,%2,%3};"
                        : "+f"(acc[mt][nt][0]), "+f"(acc[mt][nt][1]),
                          "+f"(acc[mt][nt][2]), "+f"(acc[mt][nt][3])
                        : "r"(af[mt][0]), "r"(af[mt][1]), "r"(af[mt][2]), "r"(af[mt][3]),
                          "r"(bf[nt][0]), "r"(bf[nt][1]));
        }
    }

    // epilogue
    float mi = mask[bi];
    #pragma unroll
    for (int mt = 0; mt < 2; mt++) {
        #pragma unroll
        for (int half_ = 0; half_ < 2; half_++) {
            int j = wm*32 + mt*16 + grp + half_*8;
            float mp = mi * mask[b*P_ + j];
            size_t obase = ((size_t)bi*P_ + j)*H_ + n0;
            #pragma unroll
            for (int nt = 0; nt < 4; nt++) {
                int col = wn*32 + nt*8 + thr*2;
                float2 v;
                v.x = (acc[mt][nt][half_*2+0] + g_bias[n0 + col])     * mp;
                v.y = (acc[mt][nt][half_*2+1] + g_bias[n0 + col + 1]) * mp;
                *(float2*)&out[obase + col] = v;
            }
        }
    }
}

// ---------------- launch --------------------------------------------------
extern "C" void kernel_launch(void* const* d_in, const int* in_sizes, int n_in,
                              void* d_out, int out_size)
{
    const float* F    = (const float*)d_in[0];
    const float* dist = (const float*)d_in[1];
    const float* mask = (const float*)d_in[2];
    const float* Ws1  = (const float*)d_in[3];
    const float* bs1  = (const float*)d_in[4];
    const float* Ws2  = (const float*)d_in[5];
    const float* bs2  = (const float*)d_in[6];
    const float* Wt1  = (const float*)d_in[7];
    const float* bt1  = (const float*)d_in[8];
    const float* Wt2  = (const float*)d_in[9];
    const float* bt2  = (const float*)d_in[10];
    const float* Wi1  = (const float*)d_in[11];
    const float* bi1  = (const float*)d_in[12];
    const float* Wi2  = (const float*)d_in[13];
    const float* bi2  = (const float*)d_in[14];
    const float* Wf   = (const float*)d_in[15];
    const float* bff  = (const float*)d_in[16];
    float* out = (float*)d_out;

    prep_all<<<NPROJ + NFUSE + NPACK, 256>>>(Ws2, Wt2, Wi2, Wf, bs2, bt2, bi2, bff,
                                             F, Ws1, Wt1, Wi1, bs1, bt1);
    bilinear_hi<<<dim3(NPTS, 2), 384>>>(F, bi1);
    gemm_fused<<<dim3(NPTS, H_ / DN), 384>>>(dist, mask, Ws1, out);
}

// round 15
// speedup vs baseline: 1.2294x; 1.2294x over previous
#include <cuda_runtime.h>
#include <cuda_fp16.h>
#include <cstdint>

#define B_    8
#define P_    96
#define D_    128
#define H_    256
#define NPTS  (B_*P_)          // 768
#define NPAIR (B_*P_*P_)       // 73728
#define K3    (3*H_)           // 768

// prep_all (512 threads/block): proj first (96), fuse (192), pack (32)
#define NPROJ (NPTS/8)         // 96 blocks, 8 points each, 512 thr (2 thr-halves x 4 pts)
#define NFUSE (K3/4)           // 192 blocks, 2 k-pairs each
#define NPACK (D_/4)           // 32 blocks, 2 k-pairs each

// ---------------- device scratch ----------------
__device__ __align__(16) uint32_t g_WcatP[(K3/2)*H_];  // fused (W2@Wf), half2 k-pair packed: [kp][n]
__device__ __align__(16) float    g_bias[H_];
__device__ __align__(16) uint32_t g_Wi1P[(D_/2)*H_];   // Wi1 product-half, half2 k-pair packed
__device__ __align__(16) float    g_As[NPTS*H_];
__device__ __align__(16) float    g_Bs[NPTS*H_];
__device__ __align__(16) float    g_At[NPTS*H_];
__device__ __align__(16) float    g_Bt[NPTS*H_];
__device__ __align__(16) float    g_Ci[NPTS*H_];
__device__ __align__(16) __half   g_Hi[(size_t)NPAIR*H_];  // relu'd interaction hidden, fp16, 37.7MB

__device__ __forceinline__ uint32_t pack_h2(float lo, float hi) {
    __half2 h = __floats2half2_rn(lo, hi);
    return *(uint32_t*)&h;
}

// ---------------- combined prep: point-proj + weights-fuse + wi1-pack -------
__global__ void __launch_bounds__(512) prep_all(
    const float* __restrict__ Ws2, const float* __restrict__ Wt2,
    const float* __restrict__ Wi2, const float* __restrict__ Wf,
    const float* __restrict__ bs2, const float* __restrict__ bt2,
    const float* __restrict__ bi2, const float* __restrict__ bff,
    const float* __restrict__ F,   const float* __restrict__ Ws1,
    const float* __restrict__ Wt1, const float* __restrict__ Wi1,
    const float* __restrict__ bs1, const float* __restrict__ bt1)
{
    int bx  = blockIdx.x;
    int tid = threadIdx.x;
    int h   = tid & 255;
    int hi_ = tid >> 8;            // 0 or 1

    if (bx < NPROJ) {
        // ---- per-point projections: 8 points/block, 512 threads ----
        // thread-half 0 -> points 0..3, half 1 -> points 4..7 (same h column)
        __shared__ __align__(16) float sF[8][D_];
        int p0 = bx * 8;
        for (int t = tid; t < 8*D_; t += 512) sF[t / D_][t % D_] = F[p0*D_ + t];
        __syncthreads();

        int rb = hi_ * 4;
        float as[4], bs[4], at[4], bt[4], ci[4];
        float b1 = bs1[h], b2 = bt1[h];
        #pragma unroll
        for (int r = 0; r < 4; r++) { as[r]=b1; bs[r]=0.f; at[r]=b2; bt[r]=0.f; ci[r]=0.f; }

        #pragma unroll 4
        for (int d = 0; d < D_; d++) {
            float wsa = Ws1[d*H_ + h];
            float wsb = Ws1[(D_ + d)*H_ + h];
            float wta = Wt1[d*H_ + h];
            float wtb = Wt1[(D_ + d)*H_ + h];
            float wib = Wi1[(D_ + d)*H_ + h];
            #pragma unroll
            for (int r = 0; r < 4; r++) {
                float f = sF[rb + r][d];
                as[r] = fmaf(f, wsa, as[r]);
                bs[r] = fmaf(f, wsb, bs[r]);
                at[r] = fmaf(f, wta, at[r]);
                bt[r] = fmaf(f, wtb, bt[r]);
                ci[r] = fmaf(f, wib, ci[r]);
            }
        }
        #pragma unroll
        for (int r = 0; r < 4; r++) {
            int idx = (p0 + rb + r)*H_ + h;
            g_As[idx]=as[r]; g_Bs[idx]=bs[r]; g_At[idx]=at[r]; g_Bt[idx]=bt[r]; g_Ci[idx]=ci[r];
        }
    } else if (bx < NPROJ + NFUSE) {
        // ---- fuse layer-2 with final projection: 2 k-pairs/block ----
        int kp = (bx - NPROJ) * 2 + hi_;
        int k0 = 2*kp;
        int p  = k0 >> 8;
        int kk0 = k0 & 255, kk1 = kk0 + 1;
        const float* W2  = (p == 0) ? Ws2 : ((p == 1) ? Wt2 : Wi2);
        const float* Wfp = Wf + p * H_ * H_;
        float a0 = 0.f, a1 = 0.f;
        #pragma unroll 8
        for (int m = 0; m < H_; m++) {
            float w = Wfp[m*H_ + h];
            a0 = fmaf(W2[kk0*H_ + m], w, a0);
            a1 = fmaf(W2[kk1*H_ + m], w, a1);
        }
        g_WcatP[kp*H_ + h] = pack_h2(a0, a1);

        if (kp == 0) {
            float b = bff[h];
            for (int m = 0; m < H_; m++) {
                b = fmaf(bs2[m], Wf[m*H_ + h],          b);
                b = fmaf(bt2[m], Wf[(H_   + m)*H_ + h], b);
                b = fmaf(bi2[m], Wf[(2*H_ + m)*H_ + h], b);
            }
            g_bias[h] = b;
        }
    } else {
        // ---- pack Wi1 product-half: 2 k-pairs/block ----
        int kp = (bx - (NPROJ + NFUSE)) * 2 + hi_;
        g_Wi1P[kp*H_ + h] = pack_h2(Wi1[(2*kp)*H_ + h], Wi1[(2*kp+1)*H_ + h]);
    }
}

// ---------------- kernel C: interaction hidden, fp16 mma, BK=32 -------------
// CTA = (b,i) x n-half. Hi[j,n] = relu((f_i.*f_j)@Wi1a + Ci_i + Ci_j + bi1)
// M=96, N=128, K=128 (4 iters of k32, double-buffered, 1 sync/iter).
__global__ void __launch_bounds__(384, 2) bilinear_hi(
    const float* __restrict__ F, const float* __restrict__ bi1)
{
    __shared__ __align__(16) uint32_t sP[2][16][96 + 8];    // half2, stride 104
    __shared__ __align__(16) uint32_t sW[2][16][128 + 8];   // half2, stride 136
    __shared__ float sFi[D_], sCii[128], sBi1[128];

    int bi = blockIdx.x;
    int b  = bi / P_;
    int n0 = blockIdx.y * 128;
    int tid  = threadIdx.x;
    int warp = tid >> 5, lane = tid & 31;
    int wm = warp >> 2, wn = warp & 3;      // 3 x 4
    int grp = lane >> 2, thr = lane & 3;

    for (int t = tid; t < D_; t += 384) sFi[t] = F[bi*D_ + t];
    for (int t = tid; t < 128; t += 384) {
        sCii[t] = g_Ci[bi*H_ + n0 + t];
        sBi1[t] = bi1[n0 + t];
    }
    __syncthreads();

    int j_a = tid >> 2, k_a = (tid & 3) << 3;   // j 0..95, k offset {0,8,16,24}
    const float* rowF = F + (b*P_ + j_a) * D_;

    // sW loader: 16 rows x 128 uint32 = 512 uint4; slot0 all threads, slot1 tid<128
    int w_r0 = tid >> 5,          w_c0 = (tid & 31) << 2;
    int w_r1 = (tid + 384) >> 5;  // 12..15
    bool w_act1 = tid < 128;

    float acc[2][4][4];
    #pragma unroll
    for (int mt = 0; mt < 2; mt++)
        #pragma unroll
        for (int nt = 0; nt < 4; nt++)
            #pragma unroll
            for (int c = 0; c < 4; c++) acc[mt][nt][c] = 0.f;

    // prologue prefetch (d0 = 0)
    float4 vf0 = *(const float4*)(rowF + k_a);
    float4 vf1 = *(const float4*)(rowF + k_a + 4);
    uint4  vw0 = *(const uint4*)&g_Wi1P[w_r0*H_ + n0 + w_c0];
    uint4  vw1;
    if (w_act1) vw1 = *(const uint4*)&g_Wi1P[w_r1*H_ + n0 + w_c0];

    for (int d0 = 0; d0 < D_; d0 += 32) {
        int buf = (d0 >> 5) & 1;
        int kp0 = k_a >> 1;                     // 4 k-pair rows per thread
        sP[buf][kp0+0][j_a] = pack_h2(sFi[d0+k_a+0]*vf0.x, sFi[d0+k_a+1]*vf0.y);
        sP[buf][kp0+1][j_a] = pack_h2(sFi[d0+k_a+2]*vf0.z, sFi[d0+k_a+3]*vf0.w);
        sP[buf][kp0+2][j_a] = pack_h2(sFi[d0+k_a+4]*vf1.x, sFi[d0+k_a+5]*vf1.y);
        sP[buf][kp0+3][j_a] = pack_h2(sFi[d0+k_a+6]*vf1.z, sFi[d0+k_a+7]*vf1.w);
        *(uint4*)&sW[buf][w_r0][w_c0] = vw0;
        if (w_act1) *(uint4*)&sW[buf][w_r1][w_c0] = vw1;
        __syncthreads();

        int dn = d0 + 32;
        if (dn < D_) {
            vf0 = *(const float4*)(rowF + dn + k_a);
            vf1 = *(const float4*)(rowF + dn + k_a + 4);
            vw0 = *(const uint4*)&g_Wi1P[((dn>>1) + w_r0)*H_ + n0 + w_c0];
            if (w_act1) vw1 = *(const uint4*)&g_Wi1P[((dn>>1) + w_r1)*H_ + n0 + w_c0];
        }

        #pragma unroll
        for (int s = 0; s < 2; s++) {
            int kb = s * 8;
            uint32_t af[2][4], bf[4][2];
            #pragma unroll
            for (int mt = 0; mt < 2; mt++) {
                int row = wm*32 + mt*16 + grp;
                af[mt][0] = sP[buf][kb + thr    ][row];
                af[mt][1] = sP[buf][kb + thr    ][row + 8];
                af[mt][2] = sP[buf][kb + thr + 4][row];
                af[mt][3] = sP[buf][kb + thr + 4][row + 8];
            }
            #pragma unroll
            for (int nt = 0; nt < 4; nt++) {
                int col = wn*32 + nt*8 + grp;
                bf[nt][0] = sW[buf][kb + thr    ][col];
                bf[nt][1] = sW[buf][kb + thr + 4][col];
            }
            #pragma unroll
            for (int mt = 0; mt < 2; mt++)
                #pragma unroll
                for (int nt = 0; nt < 4; nt++)
                    asm volatile(
                        "mma.sync.aligned.m16n8k16.row.col.f32.f16.f16.f32 "
                        "{%0,%1,%2,%3}, {%4,%5,%6,%7}, {%8,%9}, {%0,%1,%2,%3};"
                        : "+f"(acc[mt][nt][0]), "+f"(acc[mt][nt][1]),
                          "+f"(acc[mt][nt][2]), "+f"(acc[mt][nt][3])
                        : "r"(af[mt][0]), "r"(af[mt][1]), "r"(af[mt][2]), "r"(af[mt][3]),
                          "r"(bf[nt][0]), "r"(bf[nt][1]));
        }
    }

    // epilogue: + Ci_i + Ci_j + bi1, relu, fp16-round, store half2
    #pragma unroll
    for (int mt = 0; mt < 2; mt++) {
        #pragma unroll
        for (int half_ = 0; half_ < 2; half_++) {
            int j = wm*32 + mt*16 + grp + half_*8;
            const float* cij = g_Ci + (b*P_ + j)*H_ + n0;
            size_t obase = ((size_t)bi*P_ + j)*H_ + n0;
            #pragma unroll
            for (int nt = 0; nt < 4; nt++) {
                int col = wn*32 + nt*8 + thr*2;
                float vx = fmaxf(acc[mt][nt][half_*2+0] + sCii[col]   + cij[col]   + sBi1[col],   0.f);
                float vy = fmaxf(acc[mt][nt][half_*2+1] + sCii[col+1] + cij[col+1] + sBi1[col+1], 0.f);
                *(uint32_t*)&g_Hi[obase + col] = pack_h2(vx, vy);
            }
        }
    }
}

// ---------------- kernel D: fused GEMM, fp16 mma, BK=32 ---------------------
// CTA = (b,i) x n-half. out[j,n] = sum_k relu(H[j,k]) * Wcat[k,n] + bias, * mask.
// M=96, N=128, K=768 (24 iters of k32, double-buffered, 1 sync/iter).
#define DN 128

__global__ void __launch_bounds__(384, 2) gemm_fused(
    const float* __restrict__ dist, const float* __restrict__ mask,
    const float* __restrict__ Ws1,  float* __restrict__ out)
{
    __shared__ __align__(16) uint32_t sA[2][16][96 + 8];    // half2, stride 104
    __shared__ __align__(16) uint32_t sB[2][16][DN + 8];    // half2, stride 136
    __shared__ float sAsi[H_], sAti[H_], sW1c[H_];

    int bi = blockIdx.x;
    int b  = bi / P_;
    int n0 = blockIdx.y * DN;
    int tid  = threadIdx.x;
    int warp = tid >> 5, lane = tid & 31;
    int wm = warp >> 2, wn = warp & 3;      // 3 x 4
    int grp = lane >> 2, thr = lane & 3;

    for (int t = tid; t < H_; t += 384) {
        sAsi[t] = g_As[bi*H_ + t];
        sAti[t] = g_At[bi*H_ + t];
        sW1c[t] = Ws1[2*D_*H_ + t];        // Ws1 row 256 (distance)
    }
    __syncthreads();

    int j_a = tid >> 2, k_a = (tid & 3) << 3;   // j 0..95, k offset {0,8,16,24}
    const float*  rowBs = g_Bs + (b*P_ + j_a)*H_;
    const float*  rowBt = g_Bt + (b*P_ + j_a)*H_;
    const __half* rowHi = g_Hi + ((size_t)bi*P_ + j_a)*H_;
    float dj = dist[bi*P_ + j_a];

    int w_r0 = tid >> 5,          w_c0 = (tid & 31) << 2;
    int w_r1 = (tid + 384) >> 5;  // 12..15
    bool w_act1 = tid < 128;

    float acc[2][4][4];
    #pragma unroll
    for (int mt = 0; mt < 2; mt++)
        #pragma unroll
        for (int nt = 0; nt < 4; nt++)
            #pragma unroll
            for (int c = 0; c < 4; c++) acc[mt][nt][c] = 0.f;

    // prologue prefetch (k0 = 0). va0/va1 carry fp32 pairs for k<512; for the
    // Hi region va0 alone carries 8 halves (raw bits).
    float4 va0 = *(const float4*)(rowBs + k_a);
    float4 va1 = *(const float4*)(rowBs + k_a + 4);
    uint4  vb0 = *(const uint4*)&g_WcatP[w_r0*H_ + n0 + w_c0];
    uint4  vb1;
    if (w_act1) vb1 = *(const uint4*)&g_WcatP[w_r1*H_ + n0 + w_c0];

    for (int k0 = 0; k0 < K3; k0 += 32) {
        int buf = (k0 >> 5) & 1;
        int kp0 = k_a >> 1;
        if (k0 < 256) {
            int kk = k0 + k_a;
            sA[buf][kp0+0][j_a] = pack_h2(fmaxf(sAsi[kk+0] + va0.x + dj*sW1c[kk+0], 0.f),
                                          fmaxf(sAsi[kk+1] + va0.y + dj*sW1c[kk+1], 0.f));
            sA[buf][kp0+1][j_a] = pack_h2(fmaxf(sAsi[kk+2] + va0.z + dj*sW1c[kk+2], 0.f),
                                          fmaxf(sAsi[kk+3] + va0.w + dj*sW1c[kk+3], 0.f));
            sA[buf][kp0+2][j_a] = pack_h2(fmaxf(sAsi[kk+4] + va1.x + dj*sW1c[kk+4], 0.f),
                                          fmaxf(sAsi[kk+5] + va1.y + dj*sW1c[kk+5], 0.f));
            sA[buf][kp0+3][j_a] = pack_h2(fmaxf(sAsi[kk+6] + va1.z + dj*sW1c[kk+6], 0.f),
                                          fmaxf(sAsi[kk+7] + va1.w + dj*sW1c[kk+7], 0.f));
        } else if (k0 < 512) {
            int kk = k0 - 256 + k_a;
            sA[buf][kp0+0][j_a] = pack_h2(fmaxf(sAti[kk+0] + va0.x, 0.f),
                                          fmaxf(sAti[kk+1] + va0.y, 0.f));
            sA[buf][kp0+1][j_a] = pack_h2(fmaxf(sAti[kk+2] + va0.z, 0.f),
                                          fmaxf(sAti[kk+3] + va0.w, 0.f));
            sA[buf][kp0+2][j_a] = pack_h2(fmaxf(sAti[kk+4] + va1.x, 0.f),
                                          fmaxf(sAti[kk+5] + va1.y, 0.f));
            sA[buf][kp0+3][j_a] = pack_h2(fmaxf(sAti[kk+6] + va1.z, 0.f),
                                          fmaxf(sAti[kk+7] + va1.w, 0.f));
        } else {
            sA[buf][kp0+0][j_a] = __float_as_uint(va0.x);   // already relu'd fp16 pairs
            sA[buf][kp0+1][j_a] = __float_as_uint(va0.y);
            sA[buf][kp0+2][j_a] = __float_as_uint(va0.z);
            sA[buf][kp0+3][j_a] = __float_as_uint(va0.w);
        }
        *(uint4*)&sB[buf][w_r0][w_c0] = vb0;
        if (w_act1) *(uint4*)&sB[buf][w_r1][w_c0] = vb1;
        __syncthreads();

        int kn = k0 + 32;
        if (kn < K3) {
            if (kn < 512) {
                const float* src = (kn < 256) ? (rowBs + kn) : (rowBt + (kn - 256));
                va0 = *(const float4*)(src + k_a);
                va1 = *(const float4*)(src + k_a + 4);
            } else {
                va0 = *(const float4*)(const void*)(rowHi + (kn - 512) + k_a);
            }
            vb0 = *(const uint4*)&g_WcatP[((kn>>1) + w_r0)*H_ + n0 + w_c0];
            if (w_act1) vb1 = *(const uint4*)&g_WcatP[((kn>>1) + w_r1)*H_ + n0 + w_c0];
        }

        #pragma unroll
        for (int s = 0; s < 2; s++) {
            int kb = s * 8;
            uint32_t af[2][4], bf[4][2];
            #pragma unroll
            for (int mt = 0; mt < 2; mt++) {
                int row = wm*32 + mt*16 + grp;
                af[mt][0] = sA[buf][kb + thr    ][row];
                af[mt][1] = sA[buf][kb + thr    ][row + 8];
                af[mt][2] = sA[buf][kb + thr + 4][row];
                af[mt][3] = sA[buf][kb + thr + 4][row + 8];
            }
            #pragma unroll
            for (int nt = 0; nt < 4; nt++) {
                int col = wn*32 + nt*8 + grp;
                bf[nt][0] = sB[buf][kb + thr    ][col];
                bf[nt][1] = sB[buf][kb + thr + 4][col];
            }
            #pragma unroll
            for (int mt = 0; mt < 2; mt++)
                #pragma unroll
                for (int nt = 0; nt < 4; nt++)
                    asm volatile(
                        "mma.sync.aligned.m16n8k16.row.col.f32.f16.f16.f32 "
                        "{%0,%1,%2,%3}, {%4,%5,%6,%7}, {%8,%9}, {%0,%1,%2,%3};"
                        : "+f"(acc[mt][nt][0]), "+f"(acc[mt][nt][1]),
                          "+f"(acc[mt][nt][2]), "+f"(acc[mt][nt][3])
                        : "r"(af[mt][0]), "r"(af[mt][1]), "r"(af[mt][2]), "r"(af[mt][3]),
                          "r"(bf[nt][0]), "r"(bf[nt][1]));
        }
    }

    // epilogue
    float mi = mask[bi];
    #pragma unroll
    for (int mt = 0; mt < 2; mt++) {
        #pragma unroll
        for (int half_ = 0; half_ < 2; half_++) {
            int j = wm*32 + mt*16 + grp + half_*8;
            float mp = mi * mask[b*P_ + j];
            size_t obase = ((size_t)bi*P_ + j)*H_ + n0;
            #pragma unroll
            for (int nt = 0; nt < 4; nt++) {
                int col = wn*32 + nt*8 + thr*2;
                float2 v;
                v.x = (acc[mt][nt][half_*2+0] + g_bias[n0 + col])     * mp;
                v.y = (acc[mt][nt][half_*2+1] + g_bias[n0 + col + 1]) * mp;
                *(float2*)&out[obase + col] = v;
            }
        }
    }
}

// ---------------- launch --------------------------------------------------
extern "C" void kernel_launch(void* const* d_in, const int* in_sizes, int n_in,
                              void* d_out, int out_size)
{
    const float* F    = (const float*)d_in[0];
    const float* dist = (const float*)d_in[1];
    const float* mask = (const float*)d_in[2];
    const float* Ws1  = (const float*)d_in[3];
    const float* bs1  = (const float*)d_in[4];
    const float* Ws2  = (const float*)d_in[5];
    const float* bs2  = (const float*)d_in[6];
    const float* Wt1  = (const float*)d_in[7];
    const float* bt1  = (const float*)d_in[8];
    const float* Wt2  = (const float*)d_in[9];
    const float* bt2  = (const float*)d_in[10];
    const float* Wi1  = (const float*)d_in[11];
    const float* bi1  = (const float*)d_in[12];
    const float* Wi2  = (const float*)d_in[13];
    const float* bi2  = (const float*)d_in[14];
    const float* Wf   = (const float*)d_in[15];
    const float* bff  = (const float*)d_in[16];
    float* out = (float*)d_out;

    prep_all<<<NPROJ + NFUSE + NPACK, 512>>>(Ws2, Wt2, Wi2, Wf, bs2, bt2, bi2, bff,
                                             F, Ws1, Wt1, Wi1, bs1, bt1);
    bilinear_hi<<<dim3(NPTS, 2), 384>>>(F, bi1);
    gemm_fused<<<dim3(NPTS, H_ / DN), 384>>>(dist, mask, Ws1, out);
}

// round 16
// speedup vs baseline: 1.2939x; 1.0525x over previous
#include <cuda_runtime.h>
#include <cuda_fp16.h>
#include <cstdint>

#define B_    8
#define P_    96
#define D_    128
#define H_    256
#define NPTS  (B_*P_)          // 768
#define NPAIR (B_*P_*P_)       // 73728
#define K3    (3*H_)           // 768

// prep_all (512 threads/block): proj first (96), fuse (192), pack (32)
#define NPROJ (NPTS/8)
#define NFUSE (K3/4)
#define NPACK (D_/4)

// ---------------- device scratch ----------------
__device__ __align__(16) uint32_t g_WcatP[(K3/2)*H_];  // fused (W2@Wf), half2 k-pair packed: [kp][n]
__device__ __align__(16) float    g_bias[H_];
__device__ __align__(16) uint32_t g_Wi1P[(D_/2)*H_];   // Wi1 product-half, half2 k-pair packed
__device__ __align__(16) float    g_As[NPTS*H_];
__device__ __align__(16) float    g_Bs[NPTS*H_];
__device__ __align__(16) float    g_At[NPTS*H_];
__device__ __align__(16) float    g_Bt[NPTS*H_];
__device__ __align__(16) float    g_Ci[NPTS*H_];
__device__ __align__(16) __half   g_Hi[(size_t)NPAIR*H_];  // relu'd interaction hidden, fp16, 37.7MB

__device__ __forceinline__ uint32_t pack_h2(float lo, float hi) {
    __half2 h = __floats2half2_rn(lo, hi);
    return *(uint32_t*)&h;
}
__device__ __forceinline__ uint32_t smem_addr(const void* p) {
    return (uint32_t)__cvta_generic_to_shared(p);
}
#define CP16(dst_s, src_g) \
    asm volatile("cp.async.cg.shared.global [%0], [%1], 16;" :: "r"(dst_s), "l"(src_g) : "memory")
#define CP_COMMIT() asm volatile("cp.async.commit_group;" ::: "memory")
#define CP_WAIT0()  asm volatile("cp.async.wait_group 0;"  ::: "memory")

// ---------------- combined prep: point-proj + weights-fuse + wi1-pack -------
__global__ void __launch_bounds__(512) prep_all(
    const float* __restrict__ Ws2, const float* __restrict__ Wt2,
    const float* __restrict__ Wi2, const float* __restrict__ Wf,
    const float* __restrict__ bs2, const float* __restrict__ bt2,
    const float* __restrict__ bi2, const float* __restrict__ bff,
    const float* __restrict__ F,   const float* __restrict__ Ws1,
    const float* __restrict__ Wt1, const float* __restrict__ Wi1,
    const float* __restrict__ bs1, const float* __restrict__ bt1)
{
    int bx  = blockIdx.x;
    int tid = threadIdx.x;
    int h   = tid & 255;
    int hi_ = tid >> 8;            // 0 or 1

    if (bx < NPROJ) {
        __shared__ __align__(16) float sF[8][D_];
        int p0 = bx * 8;
        for (int t = tid; t < 8*D_; t += 512) sF[t / D_][t % D_] = F[p0*D_ + t];
        __syncthreads();

        int rb = hi_ * 4;
        float as[4], bs[4], at[4], bt[4], ci[4];
        float b1 = bs1[h], b2 = bt1[h];
        #pragma unroll
        for (int r = 0; r < 4; r++) { as[r]=b1; bs[r]=0.f; at[r]=b2; bt[r]=0.f; ci[r]=0.f; }

        #pragma unroll 4
        for (int d = 0; d < D_; d++) {
            float wsa = Ws1[d*H_ + h];
            float wsb = Ws1[(D_ + d)*H_ + h];
            float wta = Wt1[d*H_ + h];
            float wtb = Wt1[(D_ + d)*H_ + h];
            float wib = Wi1[(D_ + d)*H_ + h];
            #pragma unroll
            for (int r = 0; r < 4; r++) {
                float f = sF[rb + r][d];
                as[r] = fmaf(f, wsa, as[r]);
                bs[r] = fmaf(f, wsb, bs[r]);
                at[r] = fmaf(f, wta, at[r]);
                bt[r] = fmaf(f, wtb, bt[r]);
                ci[r] = fmaf(f, wib, ci[r]);
            }
        }
        #pragma unroll
        for (int r = 0; r < 4; r++) {
            int idx = (p0 + rb + r)*H_ + h;
            g_As[idx]=as[r]; g_Bs[idx]=bs[r]; g_At[idx]=at[r]; g_Bt[idx]=bt[r]; g_Ci[idx]=ci[r];
        }
    } else if (bx < NPROJ + NFUSE) {
        int kp = (bx - NPROJ) * 2 + hi_;
        int k0 = 2*kp;
        int p  = k0 >> 8;
        int kk0 = k0 & 255, kk1 = kk0 + 1;
        const float* W2  = (p == 0) ? Ws2 : ((p == 1) ? Wt2 : Wi2);
        const float* Wfp = Wf + p * H_ * H_;
        float a0 = 0.f, a1 = 0.f;
        #pragma unroll 8
        for (int m = 0; m < H_; m++) {
            float w = Wfp[m*H_ + h];
            a0 = fmaf(W2[kk0*H_ + m], w, a0);
            a1 = fmaf(W2[kk1*H_ + m], w, a1);
        }
        g_WcatP[kp*H_ + h] = pack_h2(a0, a1);

        if (kp == 0) {
            float b = bff[h];
            for (int m = 0; m < H_; m++) {
                b = fmaf(bs2[m], Wf[m*H_ + h],          b);
                b = fmaf(bt2[m], Wf[(H_   + m)*H_ + h], b);
                b = fmaf(bi2[m], Wf[(2*H_ + m)*H_ + h], b);
            }
            g_bias[h] = b;
        }
    } else {
        int kp = (bx - (NPROJ + NFUSE)) * 2 + hi_;
        g_Wi1P[kp*H_ + h] = pack_h2(Wi1[(2*kp)*H_ + h], Wi1[(2*kp+1)*H_ + h]);
    }
}

// ---------------- kernel C: interaction hidden, fp16 mma, BK=32, cp.async W -
__global__ void __launch_bounds__(384, 2) bilinear_hi(
    const float* __restrict__ F, const float* __restrict__ bi1)
{
    __shared__ __align__(16) uint32_t sP[2][16][96 + 8];    // half2, stride 104
    __shared__ __align__(16) uint32_t sW[2][16][128 + 8];   // half2, stride 136
    __shared__ float sFi[D_], sCii[128], sBi1[128];

    int bi = blockIdx.x;
    int b  = bi / P_;
    int n0 = blockIdx.y * 128;
    int tid  = threadIdx.x;
    int warp = tid >> 5, lane = tid & 31;
    int wm = warp >> 2, wn = warp & 3;      // 3 x 4
    int grp = lane >> 2, thr = lane & 3;

    for (int t = tid; t < D_; t += 384) sFi[t] = F[bi*D_ + t];
    for (int t = tid; t < 128; t += 384) {
        sCii[t] = g_Ci[bi*H_ + n0 + t];
        sBi1[t] = bi1[n0 + t];
    }

    int j_a = tid >> 2, k_a = (tid & 3) << 3;   // j 0..95, k offset {0,8,16,24}
    const float* rowF = F + (b*P_ + j_a) * D_;

    // sW loader geometry: slot0 all threads (rows 0..11), slot1 tid<128 (rows 12..15)
    int w_r0 = tid >> 5,          w_c0 = (tid & 31) << 2;
    int w_r1 = (tid + 384) >> 5;
    bool w_act1 = tid < 128;

    float acc[2][4][4];
    #pragma unroll
    for (int mt = 0; mt < 2; mt++)
        #pragma unroll
        for (int nt = 0; nt < 4; nt++)
            #pragma unroll
            for (int c = 0; c < 4; c++) acc[mt][nt][c] = 0.f;

    // prologue: cp.async W tile for buf0; register prefetch of F row
    CP16(smem_addr(&sW[0][w_r0][w_c0]), &g_Wi1P[w_r0*H_ + n0 + w_c0]);
    if (w_act1) CP16(smem_addr(&sW[0][w_r1][w_c0]), &g_Wi1P[w_r1*H_ + n0 + w_c0]);
    CP_COMMIT();
    float4 vf0 = *(const float4*)(rowF + k_a);
    float4 vf1 = *(const float4*)(rowF + k_a + 4);
    __syncthreads();   // sFi ready for P-tile build

    for (int d0 = 0; d0 < D_; d0 += 32) {
        int buf = (d0 >> 5) & 1;
        int kp0 = k_a >> 1;
        sP[buf][kp0+0][j_a] = pack_h2(sFi[d0+k_a+0]*vf0.x, sFi[d0+k_a+1]*vf0.y);
        sP[buf][kp0+1][j_a] = pack_h2(sFi[d0+k_a+2]*vf0.z, sFi[d0+k_a+3]*vf0.w);
        sP[buf][kp0+2][j_a] = pack_h2(sFi[d0+k_a+4]*vf1.x, sFi[d0+k_a+5]*vf1.y);
        sP[buf][kp0+3][j_a] = pack_h2(sFi[d0+k_a+6]*vf1.z, sFi[d0+k_a+7]*vf1.w);
        CP_WAIT0();
        __syncthreads();

        int dn = d0 + 32;
        if (dn < D_) {
            CP16(smem_addr(&sW[buf^1][w_r0][w_c0]), &g_Wi1P[((dn>>1) + w_r0)*H_ + n0 + w_c0]);
            if (w_act1) CP16(smem_addr(&sW[buf^1][w_r1][w_c0]), &g_Wi1P[((dn>>1) + w_r1)*H_ + n0 + w_c0]);
            CP_COMMIT();
            vf0 = *(const float4*)(rowF + dn + k_a);
            vf1 = *(const float4*)(rowF + dn + k_a + 4);
        }

        #pragma unroll
        for (int s = 0; s < 2; s++) {
            int kb = s * 8;
            uint32_t af[2][4], bf[4][2];
            #pragma unroll
            for (int mt = 0; mt < 2; mt++) {
                int row = wm*32 + mt*16 + grp;
                af[mt][0] = sP[buf][kb + thr    ][row];
                af[mt][1] = sP[buf][kb + thr    ][row + 8];
                af[mt][2] = sP[buf][kb + thr + 4][row];
                af[mt][3] = sP[buf][kb + thr + 4][row + 8];
            }
            #pragma unroll
            for (int nt = 0; nt < 4; nt++) {
                int col = wn*32 + nt*8 + grp;
                bf[nt][0] = sW[buf][kb + thr    ][col];
                bf[nt][1] = sW[buf][kb + thr + 4][col];
            }
            #pragma unroll
            for (int mt = 0; mt < 2; mt++)
                #pragma unroll
                for (int nt = 0; nt < 4; nt++)
                    asm volatile(
                        "mma.sync.aligned.m16n8k16.row.col.f32.f16.f16.f32 "
                        "{%0,%1,%2,%3}, {%4,%5,%6,%7}, {%8,%9}, {%0,%1,%2,%3};"
                        : "+f"(acc[mt][nt][0]), "+f"(acc[mt][nt][1]),
                          "+f"(acc[mt][nt][2]), "+f"(acc[mt][nt][3])
                        : "r"(af[mt][0]), "r"(af[mt][1]), "r"(af[mt][2]), "r"(af[mt][3]),
                          "r"(bf[nt][0]), "r"(bf[nt][1]));
        }
    }

    // epilogue: + Ci_i + Ci_j + bi1, relu, fp16-round, store half2
    #pragma unroll
    for (int mt = 0; mt < 2; mt++) {
        #pragma unroll
        for (int half_ = 0; half_ < 2; half_++) {
            int j = wm*32 + mt*16 + grp + half_*8;
            const float* cij = g_Ci + (b*P_ + j)*H_ + n0;
            size_t obase = ((size_t)bi*P_ + j)*H_ + n0;
            #pragma unroll
            for (int nt = 0; nt < 4; nt++) {
                int col = wn*32 + nt*8 + thr*2;
                float vx = fmaxf(acc[mt][nt][half_*2+0] + sCii[col]   + cij[col]   + sBi1[col],   0.f);
                float vy = fmaxf(acc[mt][nt][half_*2+1] + sCii[col+1] + cij[col+1] + sBi1[col+1], 0.f);
                *(uint32_t*)&g_Hi[obase + col] = pack_h2(vx, vy);
            }
        }
    }
}

// ---------------- kernel D: fused GEMM, fp16 mma, BK=32, cp.async B ---------
#define DN 128

__global__ void __launch_bounds__(384, 2) gemm_fused(
    const float* __restrict__ dist, const float* __restrict__ mask,
    const float* __restrict__ Ws1,  float* __restrict__ out)
{
    __shared__ __align__(16) uint32_t sA[2][16][96 + 8];    // half2, stride 104
    __shared__ __align__(16) uint32_t sB[2][16][DN + 8];    // half2, stride 136
    __shared__ float sAsi[H_], sAti[H_], sW1c[H_];

    int bi = blockIdx.x;
    int b  = bi / P_;
    int n0 = blockIdx.y * DN;
    int tid  = threadIdx.x;
    int warp = tid >> 5, lane = tid & 31;
    int wm = warp >> 2, wn = warp & 3;      // 3 x 4
    int grp = lane >> 2, thr = lane & 3;

    for (int t = tid; t < H_; t += 384) {
        sAsi[t] = g_As[bi*H_ + t];
        sAti[t] = g_At[bi*H_ + t];
        sW1c[t] = Ws1[2*D_*H_ + t];        // Ws1 row 256 (distance)
    }

    int j_a = tid >> 2, k_a = (tid & 3) << 3;   // j 0..95, k offset {0,8,16,24}
    const float*  rowBs = g_Bs + (b*P_ + j_a)*H_;
    const float*  rowBt = g_Bt + (b*P_ + j_a)*H_;
    const __half* rowHi = g_Hi + ((size_t)bi*P_ + j_a)*H_;
    float dj = dist[bi*P_ + j_a];

    int w_r0 = tid >> 5,          w_c0 = (tid & 31) << 2;
    int w_r1 = (tid + 384) >> 5;
    bool w_act1 = tid < 128;

    float acc[2][4][4];
    #pragma unroll
    for (int mt = 0; mt < 2; mt++)
        #pragma unroll
        for (int nt = 0; nt < 4; nt++)
            #pragma unroll
            for (int c = 0; c < 4; c++) acc[mt][nt][c] = 0.f;

    // prologue: cp.async B tile for buf0; register prefetch of A source
    CP16(smem_addr(&sB[0][w_r0][w_c0]), &g_WcatP[w_r0*H_ + n0 + w_c0]);
    if (w_act1) CP16(smem_addr(&sB[0][w_r1][w_c0]), &g_WcatP[w_r1*H_ + n0 + w_c0]);
    CP_COMMIT();
    float4 va0 = *(const float4*)(rowBs + k_a);
    float4 va1 = *(const float4*)(rowBs + k_a + 4);
    __syncthreads();   // sAsi/sAti/sW1c ready

    for (int k0 = 0; k0 < K3; k0 += 32) {
        int buf = (k0 >> 5) & 1;
        int kp0 = k_a >> 1;
        if (k0 < 256) {
            int kk = k0 + k_a;
            sA[buf][kp0+0][j_a] = pack_h2(fmaxf(sAsi[kk+0] + va0.x + dj*sW1c[kk+0], 0.f),
                                          fmaxf(sAsi[kk+1] + va0.y + dj*sW1c[kk+1], 0.f));
            sA[buf][kp0+1][j_a] = pack_h2(fmaxf(sAsi[kk+2] + va0.z + dj*sW1c[kk+2], 0.f),
                                          fmaxf(sAsi[kk+3] + va0.w + dj*sW1c[kk+3], 0.f));
            sA[buf][kp0+2][j_a] = pack_h2(fmaxf(sAsi[kk+4] + va1.x + dj*sW1c[kk+4], 0.f),
                                          fmaxf(sAsi[kk+5] + va1.y + dj*sW1c[kk+5], 0.f));
            sA[buf][kp0+3][j_a] = pack_h2(fmaxf(sAsi[kk+6] + va1.z + dj*sW1c[kk+6], 0.f),
                                          fmaxf(sAsi[kk+7] + va1.w + dj*sW1c[kk+7], 0.f));
        } else if (k0 < 512) {
            int kk = k0 - 256 + k_a;
            sA[buf][kp0+0][j_a] = pack_h2(fmaxf(sAti[kk+0] + va0.x, 0.f),
                                          fmaxf(sAti[kk+1] + va0.y, 0.f));
            sA[buf][kp0+1][j_a] = pack_h2(fmaxf(sAti[kk+2] + va0.z, 0.f),
                                          fmaxf(sAti[kk+3] + va0.w, 0.f));
            sA[buf][kp0+2][j_a] = pack_h2(fmaxf(sAti[kk+4] + va1.x, 0.f),
                                          fmaxf(sAti[kk+5] + va1.y, 0.f));
            sA[buf][kp0+3][j_a] = pack_h2(fmaxf(sAti[kk+6] + va1.z, 0.f),
                                          fmaxf(sAti[kk+7] + va1.w, 0.f));
        } else {
            sA[buf][kp0+0][j_a] = __float_as_uint(va0.x);   // already relu'd fp16 pairs
            sA[buf][kp0+1][j_a] = __float_as_uint(va0.y);
            sA[buf][kp0+2][j_a] = __float_as_uint(va0.z);
            sA[buf][kp0+3][j_a] = __float_as_uint(va0.w);
        }
        CP_WAIT0();
        __syncthreads();

        int kn = k0 + 32;
        if (kn < K3) {
            CP16(smem_addr(&sB[buf^1][w_r0][w_c0]), &g_WcatP[((kn>>1) + w_r0)*H_ + n0 + w_c0]);
            if (w_act1) CP16(smem_addr(&sB[buf^1][w_r1][w_c0]), &g_WcatP[((kn>>1) + w_r1)*H_ + n0 + w_c0]);
            CP_COMMIT();
            if (kn < 512) {
                const float* src = (kn < 256) ? (rowBs + kn) : (rowBt + (kn - 256));
                va0 = *(const float4*)(src + k_a);
                va1 = *(const float4*)(src + k_a + 4);
            } else {
                va0 = *(const float4*)(const void*)(rowHi + (kn - 512) + k_a);
            }
        }

        #pragma unroll
        for (int s = 0; s < 2; s++) {
            int kb = s * 8;
            uint32_t af[2][4], bf[4][2];
            #pragma unroll
            for (int mt = 0; mt < 2; mt++) {
                int row = wm*32 + mt*16 + grp;
                af[mt][0] = sA[buf][kb + thr    ][row];
                af[mt][1] = sA[buf][kb + thr    ][row + 8];
                af[mt][2] = sA[buf][kb + thr + 4][row];
                af[mt][3] = sA[buf][kb + thr + 4][row + 8];
            }
            #pragma unroll
            for (int nt = 0; nt < 4; nt++) {
                int col = wn*32 + nt*8 + grp;
                bf[nt][0] = sB[buf][kb + thr    ][col];
                bf[nt][1] = sB[buf][kb + thr + 4][col];
            }
            #pragma unroll
            for (int mt = 0; mt < 2; mt++)
                #pragma unroll
                for (int nt = 0; nt < 4; nt++)
                    asm volatile(
                        "mma.sync.aligned.m16n8k16.row.col.f32.f16.f16.f32 "
                        "{%0,%1,%2,%3}, {%4,%5,%6,%7}, {%8,%9}, {%0,%1,%2,%3};"
                        : "+f"(acc[mt][nt][0]), "+f"(acc[mt][nt][1]),
                          "+f"(acc[mt][nt][2]), "+f"(acc[mt][nt][3])
                        : "r"(af[mt][0]), "r"(af[mt][1]), "r"(af[mt][2]), "r"(af[mt][3]),
                          "r"(bf[nt][0]), "r"(bf[nt][1]));
        }
    }

    // epilogue
    float mi = mask[bi];
    #pragma unroll
    for (int mt = 0; mt < 2; mt++) {
        #pragma unroll
        for (int half_ = 0; half_ < 2; half_++) {
            int j = wm*32 + mt*16 + grp + half_*8;
            float mp = mi * mask[b*P_ + j];
            size_t obase = ((size_t)bi*P_ + j)*H_ + n0;
            #pragma unroll
            for (int nt = 0; nt < 4; nt++) {
                int col = wn*32 + nt*8 + thr*2;
                float2 v;
                v.x = (acc[mt][nt][half_*2+0] + g_bias[n0 + col])     * mp;
                v.y = (acc[mt][nt][half_*2+1] + g_bias[n0 + col + 1]) * mp;
                *(float2*)&out[obase + col] = v;
            }
        }
    }
}

// ---------------- launch --------------------------------------------------
extern "C" void kernel_launch(void* const* d_in, const int* in_sizes, int n_in,
                              void* d_out, int out_size)
{
    const float* F    = (const float*)d_in[0];
    const float* dist = (const float*)d_in[1];
    const float* mask = (const float*)d_in[2];
    const float* Ws1  = (const float*)d_in[3];
    const float* bs1  = (const float*)d_in[4];
    const float* Ws2  = (const float*)d_in[5];
    const float* bs2  = (const float*)d_in[6];
    const float* Wt1  = (const float*)d_in[7];
    const float* bt1  = (const float*)d_in[8];
    const float* Wt2  = (const float*)d_in[9];
    const float* bt2  = (const float*)d_in[10];
    const float* Wi1  = (const float*)d_in[11];
    const float* bi1  = (const float*)d_in[12];
    const float* Wi2  = (const float*)d_in[13];
    const float* bi2  = (const float*)d_in[14];
    const float* Wf   = (const float*)d_in[15];
    const float* bff  = (const float*)d_in[16];
    float* out = (float*)d_out;

    prep_all<<<NPROJ + NFUSE + NPACK, 512>>>(Ws2, Wt2, Wi2, Wf, bs2, bt2, bi2, bff,
                                             F, Ws1, Wt1, Wi1, bs1, bt1);
    bilinear_hi<<<dim3(NPTS, 2), 384>>>(F, bi1);
    gemm_fused<<<dim3(NPTS, H_ / DN), 384>>>(dist, mask, Ws1, out);
}